// round 17
// baseline (speedup 1.0000x reference)
#include <cuda_runtime.h>
#include <cuda_fp16.h>
#include <math.h>
#include <stdint.h>

// Problem constants
#define Bb   4
#define Ss   2048
#define Hh   768
#define NHh  12
#define HDd  64
#define MLPd 3072
#define NTOK (Bb * Ss)          // 8192
#define BHh  (Bb * NHh)         // 48

// ---------------- scratch (__device__ globals; no allocation allowed) ------
__device__ __align__(16) __half g_xnh [(size_t)NTOK * Hh];
__device__ __align__(16) __half g_qh  [(size_t)NTOK * Hh];
__device__ __align__(16) __half g_kh  [(size_t)NTOK * Hh];
__device__ __align__(16) __half g_vh  [(size_t)NTOK * Hh];
__device__ __align__(16) __half g_ctxh[(size_t)NTOK * Hh];
__device__ __align__(16) __half g_h1h [(size_t)NTOK * MLPd];
__device__ float g_x2 [(size_t)NTOK * Hh];
__device__ __align__(16) __half g_wqh[(size_t)Hh * Hh];
__device__ __align__(16) __half g_wkh[(size_t)Hh * Hh];
__device__ __align__(16) __half g_wvh[(size_t)Hh * Hh];
__device__ __align__(16) __half g_woh[(size_t)Hh * Hh];
__device__ __align__(16) __half g_w1h[(size_t)Hh * MLPd];
__device__ __align__(16) __half g_w2h[(size_t)MLPd * Hh];

// ---------------- fp16 / mma / async helpers --------------------------------
__device__ __forceinline__ uint32_t f2h2(float lo, float hi) {
    uint32_t r;
    asm("cvt.rn.f16x2.f32 %0, %1, %2;" : "=r"(r) : "f"(hi), "f"(lo));
    return r;
}

__device__ __forceinline__ uint32_t h2ex2(uint32_t x) {
    uint32_t r;
    asm("ex2.approx.f16x2 %0, %1;" : "=r"(r) : "r"(x));
    return r;
}

__device__ __forceinline__ void mma_f16(float* c, const uint32_t* a, const uint32_t* b) {
    asm volatile(
        "mma.sync.aligned.m16n8k16.row.col.f32.f16.f16.f32 "
        "{%0,%1,%2,%3}, {%4,%5,%6,%7}, {%8,%9}, {%0,%1,%2,%3};\n"
        : "+f"(c[0]), "+f"(c[1]), "+f"(c[2]), "+f"(c[3])
        : "r"(a[0]), "r"(a[1]), "r"(a[2]), "r"(a[3]), "r"(b[0]), "r"(b[1]));
}

__device__ __forceinline__ uint32_t smem_u32(const void* p) {
    uint32_t a;
    asm("{ .reg .u64 t; cvta.to.shared.u64 t, %1; cvt.u32.u64 %0, t; }" : "=r"(a) : "l"(p));
    return a;
}

#define CPA16(smaddr, gptr) \
    asm volatile("cp.async.cg.shared.global [%0], [%1], 16;" :: "r"(smaddr), "l"(gptr))
#define CPA_COMMIT()  asm volatile("cp.async.commit_group;" ::: "memory")
#define CPA_WAIT1()   asm volatile("cp.async.wait_group 1;" ::: "memory")
#define CPA_WAIT2()   asm volatile("cp.async.wait_group 2;" ::: "memory")

#define LDSM4(r0, r1, r2, r3, addr) \
    asm volatile("ldmatrix.sync.aligned.m8n8.x4.shared.b16 {%0,%1,%2,%3}, [%4];" \
                 : "=r"(r0), "=r"(r1), "=r"(r2), "=r"(r3) : "r"(addr))
#define LDSM4T(r0, r1, r2, r3, addr) \
    asm volatile("ldmatrix.sync.aligned.m8n8.x4.trans.shared.b16 {%0,%1,%2,%3}, [%4];" \
                 : "=r"(r0), "=r"(r1), "=r"(r2), "=r"(r3) : "r"(addr))

// ---------------- fp32 -> fp16 conversion, all 6 weights in one launch ------
__global__ void cvt_all(const float* __restrict__ wq, const float* __restrict__ wk,
                        const float* __restrict__ wv, const float* __restrict__ wo,
                        const float* __restrict__ w1, const float* __restrict__ w2,
                        __half* __restrict__ dq, __half* __restrict__ dk,
                        __half* __restrict__ dv, __half* __restrict__ dxo,
                        __half* __restrict__ d1, __half* __restrict__ d2) {
    const int bid = blockIdx.x;
    const float* src;
    __half* dst;
    int base;
    if      (bid < 144)  { src = wq; dst = dq;  base = bid * 4096; }
    else if (bid < 288)  { src = wk; dst = dk;  base = (bid - 144) * 4096; }
    else if (bid < 432)  { src = wv; dst = dv;  base = (bid - 288) * 4096; }
    else if (bid < 576)  { src = wo; dst = dxo; base = (bid - 432) * 4096; }
    else if (bid < 1152) { src = w1; dst = d1;  base = (bid - 576) * 4096; }
    else                 { src = w2; dst = d2;  base = (bid - 1152) * 4096; }
    const int tid = threadIdx.x;
    #pragma unroll
    for (int j = 0; j < 4; j++) {
        int idx = base + j * 1024 + tid * 4;
        float4 v = *reinterpret_cast<const float4*>(&src[idx]);
        uint2 p = { f2h2(v.x, v.y), f2h2(v.z, v.w) };
        *reinterpret_cast<uint2*>(&dst[idx]) = p;
    }
}

// ---------------- LayerNorm: warp per row (fp32 in, fp16 out) ---------------
__global__ void ln_kernel_h(const float* __restrict__ x,
                            const float* __restrict__ w,
                            const float* __restrict__ b,
                            __half* __restrict__ out) {
    const int lane = threadIdx.x & 31, warp = threadIdx.x >> 5;
    const size_t row = (size_t)blockIdx.x * 8 + warp;
    const float* xr = x + row * Hh;
    __half* orow = out + row * Hh;

    float4 v[6];
    float s = 0.f;
    #pragma unroll
    for (int i = 0; i < 6; i++) {
        v[i] = *reinterpret_cast<const float4*>(&xr[4 * (lane + 32 * i)]);
        s += (v[i].x + v[i].y) + (v[i].z + v[i].w);
    }
    #pragma unroll
    for (int o = 16; o; o >>= 1) s += __shfl_xor_sync(0xffffffffu, s, o);
    const float m = s * (1.0f / Hh);

    float ss = 0.f;
    #pragma unroll
    for (int i = 0; i < 6; i++) {
        v[i].x -= m; v[i].y -= m; v[i].z -= m; v[i].w -= m;
        ss += (v[i].x * v[i].x + v[i].y * v[i].y) +
              (v[i].z * v[i].z + v[i].w * v[i].w);
    }
    #pragma unroll
    for (int o = 16; o; o >>= 1) ss += __shfl_xor_sync(0xffffffffu, ss, o);
    const float r = rsqrtf(ss * (1.0f / Hh) + 1e-6f);

    #pragma unroll
    for (int i = 0; i < 6; i++) {
        const int c = 4 * (lane + 32 * i);
        float4 wv4 = *reinterpret_cast<const float4*>(&w[c]);
        float4 bv4 = *reinterpret_cast<const float4*>(&b[c]);
        uint2 p = { f2h2(v[i].x * r * wv4.x + bv4.x, v[i].y * r * wv4.y + bv4.y),
                    f2h2(v[i].z * r * wv4.z + bv4.z, v[i].w * r * wv4.w + bv4.w) };
        *reinterpret_cast<uint2*>(&orow[c]) = p;
    }
}

// ---------------- fp16 GEMM (N-tile 128): 6-stage cp.async ------------------
#define STAGE_BYTES 16384
#define GEMM_STAGES 6
#define GEMM_SMEM   (GEMM_STAGES * STAGE_BYTES)   // 98304

template<int EPI, int OUTH>
__device__ __forceinline__ void
gemm_body(const __half* __restrict__ A, const __half* __restrict__ B,
          const float* __restrict__ bias, const float* __restrict__ resid,
          void* __restrict__ Cv, int N, int K,
          int row0, int col0, uint32_t sb, float oscale) {
    const int tid  = threadIdx.x;
    const int lane = tid & 31, warp = tid >> 5;
    const int wm = warp & 1, wn = warp >> 1;
    const int g = lane >> 2, t = lane & 3;

    const int am  = tid >> 1;
    const int ac0 = (tid & 1) * 2;
    const int bk  = tid >> 3;
    const int bc0 = (tid & 7) * 2;
    const uint32_t a_st0 = (uint32_t)(am * 4 + ((ac0)     ^ ((am >> 1) & 3))) * 16;
    const uint32_t a_st1 = (uint32_t)(am * 4 + ((ac0 + 1) ^ ((am >> 1) & 3))) * 16;
    const uint32_t b_st0 = 8192u + (uint32_t)(bk * 16 + ((bc0)     ^ (bk & 7))) * 16;
    const uint32_t b_st1 = 8192u + (uint32_t)(bk * 16 + ((bc0 + 1) ^ (bk & 7))) * 16;
    const __half* aG = A + (size_t)(row0 + am) * K + ac0 * 8;

    const int lr = lane & 7, lj = lane >> 3;
    uint32_t aoff[2][4], boff[2][2];
    #pragma unroll
    for (int ks = 0; ks < 2; ks++) {
        #pragma unroll
        for (int mt = 0; mt < 4; mt++) {
            const int m = wm * 64 + mt * 16 + (lj & 1) * 8 + lr;
            const int c = 2 * ks + (lj >> 1);
            aoff[ks][mt] = (uint32_t)(m * 4 + (c ^ ((m >> 1) & 3))) * 16;
        }
        #pragma unroll
        for (int nt2 = 0; nt2 < 2; nt2++) {
            const int kk = ks * 16 + (lj & 1) * 8 + lr;
            const int c = wn * 4 + nt2 * 2 + (lj >> 1);
            boff[ks][nt2] = 8192u + (uint32_t)(kk * 16 + (c ^ (kk & 7))) * 16;
        }
    }

    float acc[4][4][4];
    #pragma unroll
    for (int i = 0; i < 4; i++)
        #pragma unroll
        for (int j = 0; j < 4; j++)
            #pragma unroll
            for (int l = 0; l < 4; l++) acc[i][j][l] = 0.f;

    const int nk = K / 32;
    const int np = nk / 2;

    auto load_chunk = [&](int c) {
        const int k0 = c * 32;
        const uint32_t stg = sb + (uint32_t)(c % GEMM_STAGES) * STAGE_BYTES;
        CPA16(stg + a_st0, aG + k0);
        CPA16(stg + a_st1, aG + k0 + 8);
        const __half* brow = B + (size_t)(k0 + bk) * N + col0 + bc0 * 8;
        CPA16(stg + b_st0, brow);
        CPA16(stg + b_st1, brow + 8);
    };
    auto issue2 = [&](int p) {
        if (2 * p < nk)     load_chunk(2 * p);
        if (2 * p + 1 < nk) load_chunk(2 * p + 1);
        CPA_COMMIT();
    };

    issue2(0);
    issue2(1);

    for (int p = 0; p < np; p++) {
        CPA_WAIT1();
        __syncthreads();
        issue2(p + 2);

        #pragma unroll
        for (int hc = 0; hc < 2; hc++) {
            const int c = 2 * p + hc;
            const uint32_t stg = sb + (uint32_t)(c % GEMM_STAGES) * STAGE_BYTES;
            #pragma unroll
            for (int ks = 0; ks < 2; ks++) {
                uint32_t af[4][4], bf[4][2];
                #pragma unroll
                for (int mt = 0; mt < 4; mt++)
                    LDSM4(af[mt][0], af[mt][1], af[mt][2], af[mt][3], stg + aoff[ks][mt]);
                #pragma unroll
                for (int nt2 = 0; nt2 < 2; nt2++)
                    LDSM4T(bf[2 * nt2][0], bf[2 * nt2][1],
                           bf[2 * nt2 + 1][0], bf[2 * nt2 + 1][1],
                           stg + boff[ks][nt2]);
                #pragma unroll
                for (int mt = 0; mt < 4; mt++)
                    #pragma unroll
                    for (int nt = 0; nt < 4; nt++)
                        mma_f16(acc[mt][nt], af[mt], bf[nt]);
            }
        }
    }

    #pragma unroll
    for (int mt = 0; mt < 4; mt++) {
        #pragma unroll
        for (int nt = 0; nt < 4; nt++) {
            const int r0 = row0 + wm * 64 + mt * 16 + g;
            const int c0 = col0 + wn * 32 + nt * 8 + 2 * t;
            const float bv0 = bias[c0], bv1 = bias[c0 + 1];
            float v00 = acc[mt][nt][0] + bv0;
            float v01 = acc[mt][nt][1] + bv1;
            float v10 = acc[mt][nt][2] + bv0;
            float v11 = acc[mt][nt][3] + bv1;
            if (EPI == 1) {
                float2 rr0 = *reinterpret_cast<const float2*>(&resid[(size_t)r0 * N + c0]);
                float2 rr1 = *reinterpret_cast<const float2*>(&resid[(size_t)(r0 + 8) * N + c0]);
                v00 += rr0.x; v01 += rr0.y; v10 += rr1.x; v11 += rr1.y;
            }
            if (EPI == 2) {
                v00 = 0.5f * v00 * (1.0f + erff(v00 * 0.70710678118654752f));
                v01 = 0.5f * v01 * (1.0f + erff(v01 * 0.70710678118654752f));
                v10 = 0.5f * v10 * (1.0f + erff(v10 * 0.70710678118654752f));
                v11 = 0.5f * v11 * (1.0f + erff(v11 * 0.70710678118654752f));
            }
            if (OUTH) {
                v00 *= oscale; v01 *= oscale; v10 *= oscale; v11 *= oscale;
                __half* Ch = reinterpret_cast<__half*>(Cv);
                *reinterpret_cast<uint32_t*>(&Ch[(size_t)r0 * N + c0])       = f2h2(v00, v01);
                *reinterpret_cast<uint32_t*>(&Ch[(size_t)(r0 + 8) * N + c0]) = f2h2(v10, v11);
            } else {
                float* Cf = reinterpret_cast<float*>(Cv);
                float2 o0 = { v00, v01 }, o1 = { v10, v11 };
                *reinterpret_cast<float2*>(&Cf[(size_t)r0 * N + c0])       = o0;
                *reinterpret_cast<float2*>(&Cf[(size_t)(r0 + 8) * N + c0]) = o1;
            }
        }
    }
}

template<int EPI, int OUTH>
__global__ void __launch_bounds__(256, 2)
gemm_hf(const __half* __restrict__ A, const __half* __restrict__ B,
        const float* __restrict__ bias, const float* __restrict__ resid,
        void* __restrict__ C, int N, int K) {
    extern __shared__ __align__(16) uint8_t SH[];
    gemm_body<EPI, OUTH>(A, B, bias, resid, C, N, K,
                         blockIdx.y * 128, blockIdx.x * 128, smem_u32(SH), 1.0f);
}

__global__ void __launch_bounds__(256, 2)
qkv_gemm(const __half* __restrict__ A,
         const __half* __restrict__ wq, const __half* __restrict__ wk,
         const __half* __restrict__ wv,
         const float* __restrict__ bq, const float* __restrict__ bk,
         const float* __restrict__ bv,
         __half* __restrict__ q, __half* __restrict__ k, __half* __restrict__ v,
         int N, int K) {
    extern __shared__ __align__(16) uint8_t SH[];
    const int z = blockIdx.z;
    const __half* W    = (z == 0) ? wq : (z == 1) ? wk : wv;
    const float*  bias = (z == 0) ? bq : (z == 1) ? bk : bv;
    __half*       C    = (z == 0) ? q  : (z == 1) ? k  : v;
    // Q scale = (1/8) * log2(e): softmax runs in base-2 (ex2 only, no mul).
    const float   osc  = (z == 0) ? 0.18033688011112042f : 1.0f;
    gemm_body<0, 1>(A, W, bias, nullptr, C, N, K,
                    blockIdx.y * 128, blockIdx.x * 128, smem_u32(SH), osc);
}

// ---------------- fp16 GEMM (N-tile 64): for 1.3-wave grids -----------------
// 128x64 tile, warp tile 64x16; B stage = flash-style rows of 128B
// (32 k x 64 n halves), chunk swizzle c ^ (row & 7). fp32 C + residual only.
#define STG64_BYTES 12288
#define GEMM64_SMEM (GEMM_STAGES * STG64_BYTES)   // 73728

__global__ void __launch_bounds__(256, 2)
gemm64_res(const __half* __restrict__ A, const __half* __restrict__ B,
           const float* __restrict__ bias, const float* __restrict__ resid,
           float* __restrict__ C, int N, int K) {
    extern __shared__ __align__(16) uint8_t SH[];
    const uint32_t sb = smem_u32(SH);
    const int row0 = blockIdx.y * 128, col0 = blockIdx.x * 64;

    const int tid  = threadIdx.x;
    const int lane = tid & 31, warp = tid >> 5;
    const int wm = warp & 1, wn = warp >> 1;
    const int g = lane >> 2, t = lane & 3;

    // A staging (identical to N128 body)
    const int am  = tid >> 1;
    const int ac0 = (tid & 1) * 2;
    const uint32_t a_st0 = (uint32_t)(am * 4 + ((ac0)     ^ ((am >> 1) & 3))) * 16;
    const uint32_t a_st1 = (uint32_t)(am * 4 + ((ac0 + 1) ^ ((am >> 1) & 3))) * 16;
    const __half* aG = A + (size_t)(row0 + am) * K + ac0 * 8;

    // B staging: rows of 128B (64 halves), one 16B chunk per thread
    const int bk = tid >> 3;           // 0..31 (k row)
    const int bc = tid & 7;            // 0..7  (16B chunk)
    const uint32_t b_st = 8192u + (uint32_t)(bk * 8 + (bc ^ (bk & 7))) * 16;

    // fragment offsets
    const int lr = lane & 7, lj = lane >> 3;
    const int cj = lj >> 1;
    const int knr = (lj & 1) * 8 + lr;
    uint32_t aoff[2][4], boff[2];
    #pragma unroll
    for (int ks = 0; ks < 2; ks++) {
        #pragma unroll
        for (int mt = 0; mt < 4; mt++) {
            const int m = wm * 64 + mt * 16 + (lj & 1) * 8 + lr;
            const int c = 2 * ks + cj;
            aoff[ks][mt] = (uint32_t)(m * 4 + (c ^ ((m >> 1) & 3))) * 16;
        }
        // B: rows ks*16 + knr (row&7 == lr), col chunks wn*2 + cj
        boff[ks] = 8192u + (uint32_t)((ks * 16 + knr) * 8 +
                                      ((wn * 2 + cj) ^ lr)) * 16;
    }

    float acc[4][2][4];
    #pragma unroll
    for (int i = 0; i < 4; i++)
        #pragma unroll
        for (int j = 0; j < 2; j++)
            #pragma unroll
            for (int l = 0; l < 4; l++) acc[i][j][l] = 0.f;

    const int nk = K / 32;
    const int np = nk / 2;

    auto load_chunk = [&](int c) {
        const int k0 = c * 32;
        const uint32_t stg = sb + (uint32_t)(c % GEMM_STAGES) * STG64_BYTES;
        CPA16(stg + a_st0, aG + k0);
        CPA16(stg + a_st1, aG + k0 + 8);
        CPA16(stg + b_st, B + (size_t)(k0 + bk) * N + col0 + bc * 8);
    };
    auto issue2 = [&](int p) {
        if (2 * p < nk)     load_chunk(2 * p);
        if (2 * p + 1 < nk) load_chunk(2 * p + 1);
        CPA_COMMIT();
    };

    issue2(0);
    issue2(1);

    for (int p = 0; p < np; p++) {
        CPA_WAIT1();
        __syncthreads();
        issue2(p + 2);

        #pragma unroll
        for (int hc = 0; hc < 2; hc++) {
            const int c = 2 * p + hc;
            const uint32_t stg = sb + (uint32_t)(c % GEMM_STAGES) * STG64_BYTES;
            #pragma unroll
            for (int ks = 0; ks < 2; ks++) {
                uint32_t af[4][4], bf[2][2];
                #pragma unroll
                for (int mt = 0; mt < 4; mt++)
                    LDSM4(af[mt][0], af[mt][1], af[mt][2], af[mt][3], stg + aoff[ks][mt]);
                LDSM4T(bf[0][0], bf[0][1], bf[1][0], bf[1][1], stg + boff[ks]);
                #pragma unroll
                for (int mt = 0; mt < 4; mt++)
                    #pragma unroll
                    for (int nt = 0; nt < 2; nt++)
                        mma_f16(acc[mt][nt], af[mt], bf[nt]);
            }
        }
    }

    #pragma unroll
    for (int mt = 0; mt < 4; mt++) {
        #pragma unroll
        for (int nt = 0; nt < 2; nt++) {
            const int r0 = row0 + wm * 64 + mt * 16 + g;
            const int c0 = col0 + wn * 16 + nt * 8 + 2 * t;
            const float bv0 = bias[c0], bv1 = bias[c0 + 1];
            float2 rr0 = *reinterpret_cast<const float2*>(&resid[(size_t)r0 * N + c0]);
            float2 rr1 = *reinterpret_cast<const float2*>(&resid[(size_t)(r0 + 8) * N + c0]);
            float2 o0 = { acc[mt][nt][0] + bv0 + rr0.x, acc[mt][nt][1] + bv1 + rr0.y };
            float2 o1 = { acc[mt][nt][2] + bv0 + rr1.x, acc[mt][nt][3] + bv1 + rr1.y };
            *reinterpret_cast<float2*>(&C[(size_t)r0 * N + c0])       = o0;
            *reinterpret_cast<float2*>(&C[(size_t)(r0 + 8) * N + c0]) = o1;
        }
    }
}

// ---------------- fused flash attention (unchanged from R15) ----------------
#define FQOFF 0
#define FSTG0 16384
#define FSTGB 16384
#define FLASH_SMEM (FSTG0 + 4 * FSTGB)    // 81920

__global__ void __launch_bounds__(256, 2)
flash_attn(const __half* __restrict__ q, const __half* __restrict__ k,
           const __half* __restrict__ v, __half* __restrict__ ctx) {
    extern __shared__ __align__(16) uint8_t fsm[];
    const uint32_t sb = smem_u32(fsm);

    const int bh = blockIdx.y;
    const int b = bh / NHh, h = bh % NHh;
    const int q0 = blockIdx.x * 128;
    const __half* Qb = q + (size_t)b * Ss * Hh + h * HDd;
    const __half* Kb = k + (size_t)b * Ss * Hh + h * HDd;
    const __half* Vb = v + (size_t)b * Ss * Hh + h * HDd;
    const int tid = threadIdx.x;
    const int lane = tid & 31, warp = tid >> 5;
    const int g = lane >> 2, t = lane & 3;
    const int lr = lane & 7, lj = lane >> 3;
    const int cj = lj >> 1;
    const int qrow = warp * 16;

    const int qr  = qrow + (lj & 1) * 8 + lr;
    const int knr = (lj & 1) * 8 + lr;

    const int svr = tid >> 2;
    const int svc0 = (tid & 3) * 2;
    const uint32_t kv_st0 = (uint32_t)(svr * 8 + ((svc0)     ^ (svr & 7))) * 16;
    const uint32_t kv_st1 = (uint32_t)(svr * 8 + ((svc0 + 1) ^ (svr & 7))) * 16;

    auto issue = [&](int p) {
        const int kt = p * 64;
        const uint32_t stg = sb + FSTG0 + (uint32_t)(p & 3) * FSTGB;
        const __half* krow = Kb + (size_t)(kt + svr) * Hh + svc0 * 8;
        const __half* vrow = Vb + (size_t)(kt + svr) * Hh + svc0 * 8;
        CPA16(stg + kv_st0, krow);
        CPA16(stg + kv_st1, krow + 8);
        CPA16(stg + 8192u + kv_st0, vrow);
        CPA16(stg + 8192u + kv_st1, vrow + 8);
        CPA_COMMIT();
    };

    {
        const int r = tid >> 1;
        const int c0 = (tid & 1) * 4;
        const __half* qg = Qb + (size_t)(q0 + r) * Hh + c0 * 8;
        #pragma unroll
        for (int j = 0; j < 4; j++) {
            const int c = c0 + j;
            CPA16(sb + FQOFF + (uint32_t)(r * 8 + (c ^ (r & 7))) * 16, qg + j * 8);
        }
    }
    issue(0);
    issue(1);
    issue(2);

    float o[8][4];
    #pragma unroll
    for (int i = 0; i < 8; i++)
        #pragma unroll
        for (int j = 0; j < 4; j++) o[i][j] = 0.f;
    float lacc[4] = { 0.f, 0.f, 0.f, 0.f };
    const uint32_t ones2 = 0x3C003C00u;
    const uint32_t onesb[2] = { ones2, ones2 };

    const int niter = Ss / 64;
    for (int it = 0; it < niter; it++) {
        CPA_WAIT2();
        __syncthreads();
        if (it + 3 < niter) issue(it + 3);

        const uint32_t stg = sb + FSTG0 + (uint32_t)(it & 3) * FSTGB;

        float s[8][4];
        #pragma unroll
        for (int i = 0; i < 8; i++)
            #pragma unroll
            for (int j = 0; j < 4; j++) s[i][j] = 0.f;

        #pragma unroll
        for (int ks = 0; ks < 4; ks++) {
            const uint32_t cq = (uint32_t)((ks * 2 + cj) ^ lr) * 16;
            uint32_t qa[4];
            LDSM4(qa[0], qa[1], qa[2], qa[3], sb + FQOFF + (uint32_t)(qr * 128) + cq);
            #pragma unroll
            for (int nt2 = 0; nt2 < 4; nt2++) {
                uint32_t kf0[2], kf1[2];
                const uint32_t ka = stg + (uint32_t)((nt2 * 16 + knr) * 128) + cq;
                LDSM4(kf0[0], kf1[0], kf0[1], kf1[1], ka);
                mma_f16(s[2 * nt2],     qa, kf0);
                mma_f16(s[2 * nt2 + 1], qa, kf1);
            }
        }

        uint32_t ph[8][2];
        #pragma unroll
        for (int nt = 0; nt < 8; nt++) {
            ph[nt][0] = h2ex2(f2h2(s[nt][0], s[nt][1]));
            ph[nt][1] = h2ex2(f2h2(s[nt][2], s[nt][3]));
        }

        #pragma unroll
        for (int ks = 0; ks < 4; ks++) {
            uint32_t pa[4];
            pa[0] = ph[2 * ks][0];
            pa[1] = ph[2 * ks][1];
            pa[2] = ph[2 * ks + 1][0];
            pa[3] = ph[2 * ks + 1][1];
            mma_f16(lacc, pa, onesb);
            #pragma unroll
            for (int nt2 = 0; nt2 < 4; nt2++) {
                uint32_t vf0[2], vf1[2];
                const uint32_t va = stg + 8192u +
                    (uint32_t)((ks * 16 + knr) * 128) +
                    (uint32_t)((nt2 * 2 + cj) ^ lr) * 16;
                LDSM4T(vf0[0], vf0[1], vf1[0], vf1[1], va);
                mma_f16(o[2 * nt2],     pa, vf0);
                mma_f16(o[2 * nt2 + 1], pa, vf1);
            }
        }
    }

    const float inv0 = 1.0f / lacc[0], inv1 = 1.0f / lacc[2];
    __half* outp = ctx + ((size_t)b * Ss + q0 + qrow) * Hh + h * HDd;
    #pragma unroll
    for (int nt = 0; nt < 8; nt++) {
        const int c = nt * 8 + 2 * t;
        *reinterpret_cast<uint32_t*>(&outp[(size_t)g * Hh + c]) =
            f2h2(o[nt][0] * inv0, o[nt][1] * inv0);
        *reinterpret_cast<uint32_t*>(&outp[(size_t)(g + 8) * Hh + c]) =
            f2h2(o[nt][2] * inv1, o[nt][3] * inv1);
    }
}

// ---------------- launch ----------------------------------------------------
extern "C" void kernel_launch(void* const* d_in, const int* in_sizes, int n_in,
                              void* d_out, int out_size) {
    const float* x     = (const float*)d_in[0];
    const float* ln1_w = (const float*)d_in[1];
    const float* ln1_b = (const float*)d_in[2];
    const float* wq    = (const float*)d_in[3];
    const float* bq    = (const float*)d_in[4];
    const float* wk    = (const float*)d_in[5];
    const float* bk    = (const float*)d_in[6];
    const float* wv    = (const float*)d_in[7];
    const float* bv    = (const float*)d_in[8];
    const float* wo    = (const float*)d_in[9];
    const float* bo    = (const float*)d_in[10];
    const float* ln2_w = (const float*)d_in[11];
    const float* ln2_b = (const float*)d_in[12];
    const float* w1    = (const float*)d_in[13];
    const float* b1    = (const float*)d_in[14];
    const float* w2    = (const float*)d_in[15];
    const float* b2    = (const float*)d_in[16];
    float* out = (float*)d_out;

    __half *p_xnh, *p_qh, *p_kh, *p_vh, *p_ctxh, *p_h1h;
    __half *p_wqh, *p_wkh, *p_wvh, *p_woh, *p_w1h, *p_w2h;
    float *p_x2;
    cudaGetSymbolAddress((void**)&p_xnh,  g_xnh);
    cudaGetSymbolAddress((void**)&p_qh,   g_qh);
    cudaGetSymbolAddress((void**)&p_kh,   g_kh);
    cudaGetSymbolAddress((void**)&p_vh,   g_vh);
    cudaGetSymbolAddress((void**)&p_ctxh, g_ctxh);
    cudaGetSymbolAddress((void**)&p_h1h,  g_h1h);
    cudaGetSymbolAddress((void**)&p_x2,   g_x2);
    cudaGetSymbolAddress((void**)&p_wqh,  g_wqh);
    cudaGetSymbolAddress((void**)&p_wkh,  g_wkh);
    cudaGetSymbolAddress((void**)&p_wvh,  g_wvh);
    cudaGetSymbolAddress((void**)&p_woh,  g_woh);
    cudaGetSymbolAddress((void**)&p_w1h,  g_w1h);
    cudaGetSymbolAddress((void**)&p_w2h,  g_w2h);

    cudaFuncSetAttribute(flash_attn,
                         cudaFuncAttributeMaxDynamicSharedMemorySize, FLASH_SMEM);
    cudaFuncSetAttribute(gemm_hf<2, 1>,
                         cudaFuncAttributeMaxDynamicSharedMemorySize, GEMM_SMEM);
    cudaFuncSetAttribute(qkv_gemm,
                         cudaFuncAttributeMaxDynamicSharedMemorySize, GEMM_SMEM);
    cudaFuncSetAttribute(gemm64_res,
                         cudaFuncAttributeMaxDynamicSharedMemorySize, GEMM64_SMEM);

    cvt_all<<<1728, 256>>>(wq, wk, wv, wo, w1, w2,
                           p_wqh, p_wkh, p_wvh, p_woh, p_w1h, p_w2h);

    const dim3 gQKV(Hh / 128, NTOK / 128, 3);      // (6, 64, 3)
    const dim3 gFc1(MLPd / 128, NTOK / 128);       // (24, 64)
    const dim3 g64(Hh / 64, NTOK / 128);           // (12, 64) = 768 blocks

    // --- attention sub-block ---
    ln_kernel_h<<<NTOK / 8, 256>>>(x, ln1_w, ln1_b, p_xnh);
    qkv_gemm<<<gQKV, 256, GEMM_SMEM>>>(p_xnh, p_wqh, p_wkh, p_wvh, bq, bk, bv,
                                       p_qh, p_kh, p_vh, Hh, Hh);
    flash_attn<<<dim3(Ss / 128, BHh), 256, FLASH_SMEM>>>(p_qh, p_kh, p_vh, p_ctxh);
    gemm64_res<<<g64, 256, GEMM64_SMEM>>>(p_ctxh, p_woh, bo, x, p_x2, Hh, Hh);

    // --- MLP sub-block ---
    ln_kernel_h<<<NTOK / 8, 256>>>(p_x2, ln2_w, ln2_b, p_xnh);
    gemm_hf<2, 1><<<gFc1, 256, GEMM_SMEM>>>(p_xnh, p_w1h, b1, nullptr, p_h1h, MLPd, Hh);
    gemm64_res<<<g64, 256, GEMM64_SMEM>>>(p_h1h, p_w2h, b2, p_x2, out, Hh, MLPd);
}